// round 1
// baseline (speedup 1.0000x reference)
#include <cuda_runtime.h>
#include <cstdint>
#include <cstddef>

// ---------------- configuration ----------------
#define TM 128
#define TN 32
#define TK 16
#define NTHR 256
#define MAXB 65536

// per-row coefficients: [set(x=0,y=1)][row][S1,S2,S3,S4]
__device__ float g_coef[2][MAXB][4];

// ---------------- Threefry-2x32-20 (exact JAX schedule) ----------------
__device__ __forceinline__ void threefry(uint32_t k0, uint32_t k1,
                                         uint32_t x0, uint32_t x1,
                                         uint32_t& o0, uint32_t& o1) {
    uint32_t ks2 = k0 ^ k1 ^ 0x1BD11BDAu;
    x0 += k0; x1 += k1;
#define TF_RND(r) { x0 += x1; x1 = (x1 << (r)) | (x1 >> (32 - (r))); x1 ^= x0; }
    TF_RND(13) TF_RND(15) TF_RND(26) TF_RND(6)
    x0 += k1;  x1 += ks2 + 1u;
    TF_RND(17) TF_RND(29) TF_RND(16) TF_RND(24)
    x0 += ks2; x1 += k0 + 2u;
    TF_RND(13) TF_RND(15) TF_RND(26) TF_RND(6)
    x0 += k0;  x1 += k1 + 3u;
    TF_RND(17) TF_RND(29) TF_RND(16) TF_RND(24)
    x0 += k1;  x1 += ks2 + 4u;
    TF_RND(13) TF_RND(15) TF_RND(26) TF_RND(6)
    x0 += ks2; x1 += k0 + 5u;
#undef TF_RND
    o0 = x0; o1 = x1;
}

// JAX uniform(0,1) from 32 random bits
__device__ __forceinline__ float bits_to_unit(uint32_t bits) {
    float f = __uint_as_float((bits >> 9) | 0x3f800000u) - 1.0f;
    return fmaxf(f, 0.0f);
}

// ---------------- fused GEMM + NLL coefficient reduction ----------------
// Block: TM rows x (loop over TN-col chunks), K = IN.
// blockIdx.y selects the x-set (0) or y-set (1).
__global__ __launch_bounds__(NTHR, 2)
void coef_kernel(const float* __restrict__ xin, const float* __restrict__ yin,
                 const float* __restrict__ Wmx, const float* __restrict__ bmx,
                 const float* __restrict__ Wsx, const float* __restrict__ bsx,
                 const float* __restrict__ Wmy, const float* __restrict__ bmy,
                 const float* __restrict__ Wsy, const float* __restrict__ bsy,
                 int B, int IN, int H)
{
    const int set = blockIdx.y;
    const float* __restrict__ A  = set ? yin : xin;
    const float* __restrict__ Wm = set ? Wmy : Wmx;
    const float* __restrict__ Ws = set ? Wsy : Wsx;
    const float* __restrict__ bm = set ? bmy : bmx;
    const float* __restrict__ bs = set ? bsy : bsx;
    const int r0 = blockIdx.x * TM;

    __shared__ float Xs[TK][TM];
    __shared__ float Wms[TK][TN];
    __shared__ float Wss[TK][TN];

    const int tid = threadIdx.x;
    const int tx = tid & 15;       // column group (2 cols)
    const int ty = tid >> 4;       // row group (8 rows)

    // A-tile load mapping: same row twice, k-quads {q, q+2}
    const int xr  = tid & 127;
    const int xk0 = (tid >> 7);          // 0 or 1
    const int xk1 = (tid >> 7) + 2;      // 2 or 3
    // W-tile load mapping
    const int wt  = tid & 127;
    const int wcol = wt & 31;
    const int wkq  = wt >> 5;            // 0..3
    const bool isMu = (tid < 128);

    float s1[8], s2[8], s3[8], s4[8];
#pragma unroll
    for (int r = 0; r < 8; r++) { s1[r] = 0.f; s2[r] = 0.f; s3[r] = 0.f; s4[r] = 0.f; }

    for (int nc = 0; nc < H; nc += TN) {
        float am[8][2], av[8][2];
#pragma unroll
        for (int r = 0; r < 8; r++) {
            am[r][0] = 0.f; am[r][1] = 0.f; av[r][0] = 0.f; av[r][1] = 0.f;
        }

        for (int k0 = 0; k0 < IN; k0 += TK) {
            // prefetch global tiles into registers
            float4 va0 = *(const float4*)(A + (size_t)(r0 + xr) * IN + k0 + xk0 * 4);
            float4 va1 = *(const float4*)(A + (size_t)(r0 + xr) * IN + k0 + xk1 * 4);
            const float* Wp = isMu ? Wm : Ws;
            float4 vw = *(const float4*)(Wp + (size_t)(nc + wcol) * IN + k0 + wkq * 4);

            __syncthreads();
            Xs[xk0*4 + 0][xr] = va0.x; Xs[xk0*4 + 1][xr] = va0.y;
            Xs[xk0*4 + 2][xr] = va0.z; Xs[xk0*4 + 3][xr] = va0.w;
            Xs[xk1*4 + 0][xr] = va1.x; Xs[xk1*4 + 1][xr] = va1.y;
            Xs[xk1*4 + 2][xr] = va1.z; Xs[xk1*4 + 3][xr] = va1.w;
            {
                float (*Wd)[TN] = isMu ? Wms : Wss;
                Wd[wkq*4 + 0][wcol] = vw.x; Wd[wkq*4 + 1][wcol] = vw.y;
                Wd[wkq*4 + 2][wcol] = vw.z; Wd[wkq*4 + 3][wcol] = vw.w;
            }
            __syncthreads();

#pragma unroll
            for (int k = 0; k < TK; k++) {
                float4 a0 = *(const float4*)&Xs[k][ty * 8];
                float4 a1 = *(const float4*)&Xs[k][ty * 8 + 4];
                float2 wmv = *(const float2*)&Wms[k][tx * 2];
                float2 wsv = *(const float2*)&Wss[k][tx * 2];
                float a[8] = {a0.x, a0.y, a0.z, a0.w, a1.x, a1.y, a1.z, a1.w};
#pragma unroll
                for (int r = 0; r < 8; r++) {
                    am[r][0] = fmaf(a[r], wmv.x, am[r][0]);
                    am[r][1] = fmaf(a[r], wmv.y, am[r][1]);
                    av[r][0] = fmaf(a[r], wsv.x, av[r][0]);
                    av[r][1] = fmaf(a[r], wsv.y, av[r][1]);
                }
            }
        }

        // epilogue: bias + exp + NLL partial sums
        float bmv0 = bm[nc + tx*2], bmv1 = bm[nc + tx*2 + 1];
        float bsv0 = bs[nc + tx*2], bsv1 = bs[nc + tx*2 + 1];
#pragma unroll
        for (int r = 0; r < 8; r++) {
#pragma unroll
            for (int c = 0; c < 2; c++) {
                float m = am[r][c] + (c ? bmv1 : bmv0);
                float v = expf(av[r][c] + (c ? bsv1 : bsv0));
                v = fmaxf(v, 1e-6f);           // GaussianNLLLoss eps clamp
                float lg = logf(v);
                float rc = 1.0f / v;
                s1[r] += lg;
                s2[r] += rc;
                s3[r] += m * rc;
                s4[r] += m * m * rc;
            }
        }
    }

    // reduce across the 16 tx lanes (same-row threads sit in 16-lane halves of a warp)
#pragma unroll
    for (int off = 1; off < 16; off <<= 1) {
#pragma unroll
        for (int r = 0; r < 8; r++) {
            s1[r] += __shfl_xor_sync(0xffffffffu, s1[r], off);
            s2[r] += __shfl_xor_sync(0xffffffffu, s2[r], off);
            s3[r] += __shfl_xor_sync(0xffffffffu, s3[r], off);
            s4[r] += __shfl_xor_sync(0xffffffffu, s4[r], off);
        }
    }
    if (tx == 0) {
#pragma unroll
        for (int r = 0; r < 8; r++) {
            int row = r0 + ty * 8 + r;
            if (row < B) {
                g_coef[set][row][0] = s1[r];
                g_coef[set][row][1] = s2[r];
                g_coef[set][row][2] = s3[r];
                g_coef[set][row][3] = s4[r];
            }
        }
    }
}

// ---------------- per-row rejection sampling (JAX threefry, partitionable mode) ----------------
__global__ void sample_kernel(float* __restrict__ out, int B, float invH)
{
    int i = blockIdx.x * blockDim.x + threadIdx.x;
    if (i >= B) return;

    float s1x = g_coef[0][i][0], s2x = g_coef[0][i][1];
    float s3x = g_coef[0][i][2], s4x = g_coef[0][i][3];
    float s1y = g_coef[1][i][0], s2y = g_coef[1][i][1];
    float s3y = g_coef[1][i][2], s4y = g_coef[1][i][3];

    // nll(xi) = a + b*xi + c*xi^2
    float ax = 0.5f * (s1x + s4x) * invH;
    float bxc = -s3x * invH;
    float cx = 0.5f * s2x * invH;
    float ay = 0.5f * (s1y + s4y) * invH;
    float byc = -s3y * invH;
    float cy = 0.5f * s2y * invH;

    // row key: split(key(42), B)[i] = threefry((0,42), (0, i))  [partitionable foldlike]
    uint32_t k0, k1;
    threefry(0u, 42u, 0u, (uint32_t)i, k0, k1);

    float xi = 0.0f;
    for (int it = 0; it < 4096; ++it) {
        // split(k, 3): new keys j=0,1,2 via threefry(k, (0, j))
        uint32_t n0, n1, p0, p1, q0, q1;
        threefry(k0, k1, 0u, 0u, n0, n1);   // next loop key
        threefry(k0, k1, 0u, 1u, p0, p1);   // k1 -> u
        threefry(k0, k1, 0u, 2u, q0, q1);   // k2 -> xi
        // scalar random_bits (partitionable): out0 ^ out1 of threefry(key, (0,0))
        uint32_t ub0, ub1, xb0, xb1;
        threefry(p0, p1, 0u, 0u, ub0, ub1);
        threefry(q0, q1, 0u, 0u, xb0, xb1);
        float u  = bits_to_unit(ub0 ^ ub1);
        float x2 = bits_to_unit(xb0 ^ xb1);
        xi = 2.0f * x2 - 1.0f;

        float qx = fmaf(fmaf(cx, xi, bxc), xi, ax);
        float qy = fmaf(fmaf(cy, xi, byc), xi, ay);
        float q  = qx * qy;

        k0 = n0; k1 = n1;
        if (u >= q) break;
    }
    out[i] = fminf(fmaxf(xi, 1e-5f), 10.0f);
}

// ---------------- launch ----------------
extern "C" void kernel_launch(void* const* d_in, const int* in_sizes, int n_in,
                              void* d_out, int out_size)
{
    const float* x   = (const float*)d_in[0];
    const float* y   = (const float*)d_in[1];
    const float* Wmx = (const float*)d_in[2];
    const float* bmx = (const float*)d_in[3];
    const float* Wsx = (const float*)d_in[4];
    const float* bsx = (const float*)d_in[5];
    const float* Wmy = (const float*)d_in[6];
    const float* bmy = (const float*)d_in[7];
    const float* Wsy = (const float*)d_in[8];
    const float* bsy = (const float*)d_in[9];

    int H  = in_sizes[3];
    int IN = in_sizes[2] / H;
    int B  = in_sizes[0] / IN;

    dim3 grid((B + TM - 1) / TM, 2);
    coef_kernel<<<grid, NTHR>>>(x, y, Wmx, bmx, Wsx, bsx, Wmy, bmy, Wsy, bsy, B, IN, H);

    int thr = 256;
    sample_kernel<<<(B + thr - 1) / thr, thr>>>((float*)d_out, B, 1.0f / (float)H);
}

// round 2
// speedup vs baseline: 1.0007x; 1.0007x over previous
#include <cuda_runtime.h>
#include <cstdint>
#include <cstddef>

// ---------------- configuration ----------------
#define TM 128
#define TN 32
#define TK 16
#define NTHR 256
#define MAXB 65536

// per-row coefficients: [set(x=0,y=1)][row][S1,S2,S3,S4]
__device__ float g_coef[2][MAXB][4];

// ---------------- Threefry-2x32-20 (exact JAX schedule) ----------------
__device__ __forceinline__ void threefry(uint32_t k0, uint32_t k1,
                                         uint32_t x0, uint32_t x1,
                                         uint32_t& o0, uint32_t& o1) {
    uint32_t ks2 = k0 ^ k1 ^ 0x1BD11BDAu;
    x0 += k0; x1 += k1;
#define TF_RND(r) { x0 += x1; x1 = (x1 << (r)) | (x1 >> (32 - (r))); x1 ^= x0; }
    TF_RND(13) TF_RND(15) TF_RND(26) TF_RND(6)
    x0 += k1;  x1 += ks2 + 1u;
    TF_RND(17) TF_RND(29) TF_RND(16) TF_RND(24)
    x0 += ks2; x1 += k0 + 2u;
    TF_RND(13) TF_RND(15) TF_RND(26) TF_RND(6)
    x0 += k0;  x1 += k1 + 3u;
    TF_RND(17) TF_RND(29) TF_RND(16) TF_RND(24)
    x0 += k1;  x1 += ks2 + 4u;
    TF_RND(13) TF_RND(15) TF_RND(26) TF_RND(6)
    x0 += ks2; x1 += k0 + 5u;
#undef TF_RND
    o0 = x0; o1 = x1;
}

// JAX uniform(0,1) from 32 random bits
__device__ __forceinline__ float bits_to_unit(uint32_t bits) {
    float f = __uint_as_float((bits >> 9) | 0x3f800000u) - 1.0f;
    return fmaxf(f, 0.0f);
}

// ---------------- fused GEMM + NLL coefficient reduction ----------------
// Block: TM rows x (loop over TN-col chunks), K = IN.
// blockIdx.y selects the x-set (0) or y-set (1).
__global__ __launch_bounds__(NTHR, 2)
void coef_kernel(const float* __restrict__ xin, const float* __restrict__ yin,
                 const float* __restrict__ Wmx, const float* __restrict__ bmx,
                 const float* __restrict__ Wsx, const float* __restrict__ bsx,
                 const float* __restrict__ Wmy, const float* __restrict__ bmy,
                 const float* __restrict__ Wsy, const float* __restrict__ bsy,
                 int B, int IN, int H)
{
    const int set = blockIdx.y;
    const float* __restrict__ A  = set ? yin : xin;
    const float* __restrict__ Wm = set ? Wmy : Wmx;
    const float* __restrict__ Ws = set ? Wsy : Wsx;
    const float* __restrict__ bm = set ? bmy : bmx;
    const float* __restrict__ bs = set ? bsy : bsx;
    const int r0 = blockIdx.x * TM;

    __shared__ float Xs[TK][TM];
    __shared__ float Wms[TK][TN];
    __shared__ float Wss[TK][TN];

    const int tid = threadIdx.x;
    const int tx = tid & 15;       // column group (2 cols)
    const int ty = tid >> 4;       // row group (8 rows)

    // A-tile load mapping: same row twice, k-quads {q, q+2}
    const int xr  = tid & 127;
    const int xk0 = (tid >> 7);          // 0 or 1
    const int xk1 = (tid >> 7) + 2;      // 2 or 3
    // W-tile load mapping
    const int wt  = tid & 127;
    const int wcol = wt & 31;
    const int wkq  = wt >> 5;            // 0..3
    const bool isMu = (tid < 128);

    float s1[8], s2[8], s3[8], s4[8];
#pragma unroll
    for (int r = 0; r < 8; r++) { s1[r] = 0.f; s2[r] = 0.f; s3[r] = 0.f; s4[r] = 0.f; }

    for (int nc = 0; nc < H; nc += TN) {
        float am[8][2], av[8][2];
#pragma unroll
        for (int r = 0; r < 8; r++) {
            am[r][0] = 0.f; am[r][1] = 0.f; av[r][0] = 0.f; av[r][1] = 0.f;
        }

        for (int k0 = 0; k0 < IN; k0 += TK) {
            // prefetch global tiles into registers
            float4 va0 = *(const float4*)(A + (size_t)(r0 + xr) * IN + k0 + xk0 * 4);
            float4 va1 = *(const float4*)(A + (size_t)(r0 + xr) * IN + k0 + xk1 * 4);
            const float* Wp = isMu ? Wm : Ws;
            float4 vw = *(const float4*)(Wp + (size_t)(nc + wcol) * IN + k0 + wkq * 4);

            __syncthreads();
            Xs[xk0*4 + 0][xr] = va0.x; Xs[xk0*4 + 1][xr] = va0.y;
            Xs[xk0*4 + 2][xr] = va0.z; Xs[xk0*4 + 3][xr] = va0.w;
            Xs[xk1*4 + 0][xr] = va1.x; Xs[xk1*4 + 1][xr] = va1.y;
            Xs[xk1*4 + 2][xr] = va1.z; Xs[xk1*4 + 3][xr] = va1.w;
            {
                float (*Wd)[TN] = isMu ? Wms : Wss;
                Wd[wkq*4 + 0][wcol] = vw.x; Wd[wkq*4 + 1][wcol] = vw.y;
                Wd[wkq*4 + 2][wcol] = vw.z; Wd[wkq*4 + 3][wcol] = vw.w;
            }
            __syncthreads();

#pragma unroll
            for (int k = 0; k < TK; k++) {
                float4 a0 = *(const float4*)&Xs[k][ty * 8];
                float4 a1 = *(const float4*)&Xs[k][ty * 8 + 4];
                float2 wmv = *(const float2*)&Wms[k][tx * 2];
                float2 wsv = *(const float2*)&Wss[k][tx * 2];
                float a[8] = {a0.x, a0.y, a0.z, a0.w, a1.x, a1.y, a1.z, a1.w};
#pragma unroll
                for (int r = 0; r < 8; r++) {
                    am[r][0] = fmaf(a[r], wmv.x, am[r][0]);
                    am[r][1] = fmaf(a[r], wmv.y, am[r][1]);
                    av[r][0] = fmaf(a[r], wsv.x, av[r][0]);
                    av[r][1] = fmaf(a[r], wsv.y, av[r][1]);
                }
            }
        }

        // epilogue: bias + exp + NLL partial sums
        float bmv0 = bm[nc + tx*2], bmv1 = bm[nc + tx*2 + 1];
        float bsv0 = bs[nc + tx*2], bsv1 = bs[nc + tx*2 + 1];
#pragma unroll
        for (int r = 0; r < 8; r++) {
#pragma unroll
            for (int c = 0; c < 2; c++) {
                float m = am[r][c] + (c ? bmv1 : bmv0);
                float v = expf(av[r][c] + (c ? bsv1 : bsv0));
                v = fmaxf(v, 1e-6f);           // GaussianNLLLoss eps clamp
                float lg = logf(v);
                float rc = 1.0f / v;
                s1[r] += lg;
                s2[r] += rc;
                s3[r] += m * rc;
                s4[r] += m * m * rc;
            }
        }
    }

    // reduce across the 16 tx lanes (same-row threads sit in 16-lane halves of a warp)
#pragma unroll
    for (int off = 1; off < 16; off <<= 1) {
#pragma unroll
        for (int r = 0; r < 8; r++) {
            s1[r] += __shfl_xor_sync(0xffffffffu, s1[r], off);
            s2[r] += __shfl_xor_sync(0xffffffffu, s2[r], off);
            s3[r] += __shfl_xor_sync(0xffffffffu, s3[r], off);
            s4[r] += __shfl_xor_sync(0xffffffffu, s4[r], off);
        }
    }
    if (tx == 0) {
#pragma unroll
        for (int r = 0; r < 8; r++) {
            int row = r0 + ty * 8 + r;
            if (row < B) {
                g_coef[set][row][0] = s1[r];
                g_coef[set][row][1] = s2[r];
                g_coef[set][row][2] = s3[r];
                g_coef[set][row][3] = s4[r];
            }
        }
    }
}

// ---------------- per-row rejection sampling (JAX threefry, partitionable mode) ----------------
__global__ void sample_kernel(float* __restrict__ out, int B, float invH)
{
    int i = blockIdx.x * blockDim.x + threadIdx.x;
    if (i >= B) return;

    float s1x = g_coef[0][i][0], s2x = g_coef[0][i][1];
    float s3x = g_coef[0][i][2], s4x = g_coef[0][i][3];
    float s1y = g_coef[1][i][0], s2y = g_coef[1][i][1];
    float s3y = g_coef[1][i][2], s4y = g_coef[1][i][3];

    // nll(xi) = a + b*xi + c*xi^2
    float ax = 0.5f * (s1x + s4x) * invH;
    float bxc = -s3x * invH;
    float cx = 0.5f * s2x * invH;
    float ay = 0.5f * (s1y + s4y) * invH;
    float byc = -s3y * invH;
    float cy = 0.5f * s2y * invH;

    // row key: split(key(42), B)[i] = threefry((0,42), (0, i))  [partitionable foldlike]
    uint32_t k0, k1;
    threefry(0u, 42u, 0u, (uint32_t)i, k0, k1);

    float xi = 0.0f;
    for (int it = 0; it < 4096; ++it) {
        // split(k, 3): new keys j=0,1,2 via threefry(k, (0, j))
        uint32_t n0, n1, p0, p1, q0, q1;
        threefry(k0, k1, 0u, 0u, n0, n1);   // next loop key
        threefry(k0, k1, 0u, 1u, p0, p1);   // k1 -> u
        threefry(k0, k1, 0u, 2u, q0, q1);   // k2 -> xi
        // scalar random_bits (partitionable): out0 ^ out1 of threefry(key, (0,0))
        uint32_t ub0, ub1, xb0, xb1;
        threefry(p0, p1, 0u, 0u, ub0, ub1);
        threefry(q0, q1, 0u, 0u, xb0, xb1);
        float u  = bits_to_unit(ub0 ^ ub1);
        float x2 = bits_to_unit(xb0 ^ xb1);
        xi = 2.0f * x2 - 1.0f;

        float qx = fmaf(fmaf(cx, xi, bxc), xi, ax);
        float qy = fmaf(fmaf(cy, xi, byc), xi, ay);
        float q  = qx * qy;

        k0 = n0; k1 = n1;
        if (u >= q) break;
    }
    out[i] = fminf(fmaxf(xi, 1e-5f), 10.0f);
}

// ---------------- launch ----------------
extern "C" void kernel_launch(void* const* d_in, const int* in_sizes, int n_in,
                              void* d_out, int out_size)
{
    const float* x   = (const float*)d_in[0];
    const float* y   = (const float*)d_in[1];
    const float* Wmx = (const float*)d_in[2];
    const float* bmx = (const float*)d_in[3];
    const float* Wsx = (const float*)d_in[4];
    const float* bsx = (const float*)d_in[5];
    const float* Wmy = (const float*)d_in[6];
    const float* bmy = (const float*)d_in[7];
    const float* Wsy = (const float*)d_in[8];
    const float* bsy = (const float*)d_in[9];

    int H  = in_sizes[3];
    int IN = in_sizes[2] / H;
    int B  = in_sizes[0] / IN;

    dim3 grid((B + TM - 1) / TM, 2);
    coef_kernel<<<grid, NTHR>>>(x, y, Wmx, bmx, Wsx, bsx, Wmy, bmy, Wsy, bsy, B, IN, H);

    int thr = 256;
    sample_kernel<<<(B + thr - 1) / thr, thr>>>((float*)d_out, B, 1.0f / (float)H);
}